// round 11
// baseline (speedup 1.0000x reference)
#include <cuda_runtime.h>
#include <cstdint>
#include <math.h>

// Problem constants
#define B_   8
#define T_   4
#define C_   512
#define H_   32
#define W_   32
#define HW_  1024
#define BT_  32          // B_*T_
#define NPART 64         // channel partitions per t
#define CPP   (C_/NPART) // 8 channels per block
#define HP_  28
#define WP_  28
#define NP_  784         // 28*28
#define BN_EPS 1e-5f
#define BSTRIDE ((size_t)T_ * C_ * HW_)   // elements between consecutive b
#define BSTR4   (BSTRIDE/4)               // in float4 units
#define NTHR 512

// Scratch (allocation-free rule: __device__ globals)
__device__ float g_part[NPART][BT_ * HW_];   // 8 MB
__device__ float g_d2[BT_ * HW_];            // 128 KB

// ---------------------------------------------------------------------------
// Fused kernel: ONE DRAM pass + hot-L2 re-read, TWO channels per barrier.
// grid: T_*NPART = 256 blocks (2/SM on most SMs), 512 threads.
// Block (t,p) owns 8 channels = 4 phases x 2 channels. Per phase:
//   stats c0 + stats c1 (streamed loads, 8 running sums)
//   warp shuffle-reduce x8, lane0 -> smem
//   ONE barrier (parity double-buffered)
//   all-warp combine x8 -> A0,B0,D0,A1,B1,D1
//   d^2 for c0 and c1: re-load from L2 (just streamed -> hot), accumulate.
// Halves barrier count vs R9; same per-channel collective cost.
// beta cancels exactly in (l_bn - r_bn).
// ---------------------------------------------------------------------------
__global__ __launch_bounds__(NTHR, 2) void fused_kernel(
    const float* __restrict__ l, const float* __restrict__ r,
    const float* __restrict__ gamma)
{
    const int t   = blockIdx.x >> 6;        // / NPART
    const int p   = blockIdx.x & (NPART-1);
    const int tid = threadIdx.x;
    const int lane = tid & 31;
    const int wid  = tid >> 5;              // 0..15

    // This thread's 4 float4 slots: s_i = tid + i*512 -> (b, hw4)
    int bvec[4], hw4[4];
    size_t offb[4];
    #pragma unroll
    for (int i = 0; i < 4; i++) {
        const int s = tid + i * NTHR;
        bvec[i] = s >> 8;
        hw4[i]  = s & 255;
        offb[i] = (size_t)bvec[i] * BSTR4 + hw4[i];
    }

    // 8 warp-sum channels x 16 warps x 2 parity
    __shared__ float wsum[2][8][16];
    __shared__ float sgamma[CPP];
    if (tid < CPP) sgamma[tid] = gamma[p * CPP + tid];

    float acc[16];
    #pragma unroll
    for (int k = 0; k < 16; k++) acc[k] = 0.f;

    const float4* l4 = reinterpret_cast<const float4*>(l);
    const float4* r4 = reinterpret_cast<const float4*>(r);

    #pragma unroll 1
    for (int ph = 0; ph < CPP / 2; ph++) {
        const int c0 = p * CPP + 2 * ph;
        const size_t chb0 = ((size_t)(t * C_ + c0)) * (HW_ / 4);
        const size_t chb1 = chb0 + (HW_ / 4);

        // ---- stats for both channels (streamed; data not retained)
        float s0l = 0.f, q0l = 0.f, s0r = 0.f, q0r = 0.f;
        float s1l = 0.f, q1l = 0.f, s1r = 0.f, q1r = 0.f;
        #pragma unroll
        for (int i = 0; i < 4; i++) {
            float4 a = l4[offb[i] + chb0];
            float4 b = r4[offb[i] + chb0];
            float4 cc = l4[offb[i] + chb1];
            float4 dd = r4[offb[i] + chb1];
            s0l += (a.x + a.y) + (a.z + a.w);
            s0r += (b.x + b.y) + (b.z + b.w);
            s1l += (cc.x + cc.y) + (cc.z + cc.w);
            s1r += (dd.x + dd.y) + (dd.z + dd.w);
            q0l = fmaf(a.x, a.x, q0l); q0l = fmaf(a.y, a.y, q0l);
            q0l = fmaf(a.z, a.z, q0l); q0l = fmaf(a.w, a.w, q0l);
            q0r = fmaf(b.x, b.x, q0r); q0r = fmaf(b.y, b.y, q0r);
            q0r = fmaf(b.z, b.z, q0r); q0r = fmaf(b.w, b.w, q0r);
            q1l = fmaf(cc.x, cc.x, q1l); q1l = fmaf(cc.y, cc.y, q1l);
            q1l = fmaf(cc.z, cc.z, q1l); q1l = fmaf(cc.w, cc.w, q1l);
            q1r = fmaf(dd.x, dd.x, q1r); q1r = fmaf(dd.y, dd.y, q1r);
            q1r = fmaf(dd.z, dd.z, q1r); q1r = fmaf(dd.w, dd.w, q1r);
        }

        // ---- warp shuffle reductions (8 values)
        #pragma unroll
        for (int o = 16; o > 0; o >>= 1) {
            s0l += __shfl_xor_sync(0xffffffffu, s0l, o);
            q0l += __shfl_xor_sync(0xffffffffu, q0l, o);
            s0r += __shfl_xor_sync(0xffffffffu, s0r, o);
            q0r += __shfl_xor_sync(0xffffffffu, q0r, o);
            s1l += __shfl_xor_sync(0xffffffffu, s1l, o);
            q1l += __shfl_xor_sync(0xffffffffu, q1l, o);
            s1r += __shfl_xor_sync(0xffffffffu, s1r, o);
            q1r += __shfl_xor_sync(0xffffffffu, q1r, o);
        }

        const int par = ph & 1;
        if (lane == 0) {
            wsum[par][0][wid] = s0l; wsum[par][1][wid] = q0l;
            wsum[par][2][wid] = s0r; wsum[par][3][wid] = q0r;
            wsum[par][4][wid] = s1l; wsum[par][5][wid] = q1l;
            wsum[par][6][wid] = s1r; wsum[par][7][wid] = q1r;
        }
        __syncthreads();   // the ONLY barrier per 2-channel phase

        // ---- every warp combines the 16 warp-sums for all 8 quantities
        float v[8];
        #pragma unroll
        for (int k = 0; k < 8; k++)
            v[k] = (lane < 16) ? wsum[par][k][lane] : 0.f;
        #pragma unroll
        for (int o = 8; o > 0; o >>= 1) {
            #pragma unroll
            for (int k = 0; k < 8; k++)
                v[k] += __shfl_xor_sync(0xffffffffu, v[k], o);
        }
        #pragma unroll
        for (int k = 0; k < 8; k++)
            v[k] = __shfl_sync(0xffffffffu, v[k], 0);

        const float inv_n = 1.f / (float)(B_ * HW_);   // 1/8192
        float mu0l = v[0] * inv_n, mu0r = v[2] * inv_n;
        float mu1l = v[4] * inv_n, mu1r = v[6] * inv_n;
        float var0l = fmaf(-mu0l, mu0l, v[1] * inv_n);
        float var0r = fmaf(-mu0r, mu0r, v[3] * inv_n);
        float var1l = fmaf(-mu1l, mu1l, v[5] * inv_n);
        float var1r = fmaf(-mu1r, mu1r, v[7] * inv_n);
        float g0 = sgamma[2 * ph], g1 = sgamma[2 * ph + 1];
        float A0 = g0 / sqrtf(var0l + BN_EPS);
        float B0 = g0 / sqrtf(var0r + BN_EPS);
        float D0 = A0 * mu0l - B0 * mu0r;
        float A1 = g1 / sqrtf(var1l + BN_EPS);
        float B1 = g1 / sqrtf(var1r + BN_EPS);
        float D1 = A1 * mu1l - B1 * mu1r;

        // ---- d^2 passes: re-read both channels (hot in L2), accumulate
        #pragma unroll
        for (int i = 0; i < 4; i++) {
            float4 a = l4[offb[i] + chb0];
            float4 b = r4[offb[i] + chb0];
            float d;
            d = fmaf(A0, a.x, fmaf(-B0, b.x, -D0)); acc[i*4+0] = fmaf(d, d, acc[i*4+0]);
            d = fmaf(A0, a.y, fmaf(-B0, b.y, -D0)); acc[i*4+1] = fmaf(d, d, acc[i*4+1]);
            d = fmaf(A0, a.z, fmaf(-B0, b.z, -D0)); acc[i*4+2] = fmaf(d, d, acc[i*4+2]);
            d = fmaf(A0, a.w, fmaf(-B0, b.w, -D0)); acc[i*4+3] = fmaf(d, d, acc[i*4+3]);
        }
        #pragma unroll
        for (int i = 0; i < 4; i++) {
            float4 a = l4[offb[i] + chb1];
            float4 b = r4[offb[i] + chb1];
            float d;
            d = fmaf(A1, a.x, fmaf(-B1, b.x, -D1)); acc[i*4+0] = fmaf(d, d, acc[i*4+0]);
            d = fmaf(A1, a.y, fmaf(-B1, b.y, -D1)); acc[i*4+1] = fmaf(d, d, acc[i*4+1]);
            d = fmaf(A1, a.z, fmaf(-B1, b.z, -D1)); acc[i*4+2] = fmaf(d, d, acc[i*4+2]);
            d = fmaf(A1, a.w, fmaf(-B1, b.w, -D1)); acc[i*4+3] = fmaf(d, d, acc[i*4+3]);
        }
    }

    // ---- write partials: g_part[p][(b*T+t)*1024 + hw] as float4
    float4* gp = reinterpret_cast<float4*>(g_part[p]);
    #pragma unroll
    for (int i = 0; i < 4; i++) {
        gp[(bvec[i] * T_ + t) * (HW_/4) + hw4[i]] =
            make_float4(acc[i*4+0], acc[i*4+1], acc[i*4+2], acc[i*4+3]);
    }
}

// ---------------------------------------------------------------------------
// Reduce: collapse 64 partials -> g_d2. grid: 256 blocks (bt x 8 segments),
// 1024 threads as (kg = tid>>7 in [0,8), hw_local = tid&127). Each thread
// sums 8 partitions; smem combine of 8 groups. Deterministic order.
// ---------------------------------------------------------------------------
__global__ __launch_bounds__(1024) void reduce_kernel()
{
    const int bt = blockIdx.x >> 3;
    const int q  = blockIdx.x & 7;
    const int hw_local = threadIdx.x & 127;
    const int kg = threadIdx.x >> 7;          // 0..7
    const int hw = q * 128 + hw_local;

    float s = 0.f;
    #pragma unroll
    for (int i = 0; i < 8; i++)
        s += g_part[kg * 8 + i][bt * HW_ + hw];

    __shared__ float red[8][128];
    red[kg][hw_local] = s;
    __syncthreads();

    if (kg == 0) {
        float tot = 0.f;
        #pragma unroll
        for (int k = 0; k < 8; k++) tot += red[k][hw_local];
        g_d2[bt * HW_ + hw] = tot;
    }
}

// ---------------------------------------------------------------------------
// Finalize: 5x5 window sum, sqrt, max + first-argmin.
// grid: 32 blocks (one per (b,t)), 1024 threads.
// Output layout (float32, tuple order):
//   [0,32) values (B,T) | [32,96) coords (B,T,2) [x,y] | [96,25184) heatmap
// ---------------------------------------------------------------------------
__global__ __launch_bounds__(1024) void finalize_kernel(float* __restrict__ out)
{
    const int bt  = blockIdx.x;
    const int tid = threadIdx.x;

    __shared__ float d2[HW_];
    d2[tid] = g_d2[bt * HW_ + tid];
    __syncthreads();

    float mymax = -3.0e38f;
    float mymin =  3.0e38f;
    int   myidx = 0x7fffffff;

    if (tid < NP_) {
        const int y = tid / WP_;
        const int x = tid % WP_;
        float ws = 0.f;
        #pragma unroll
        for (int dy = 0; dy < 5; dy++)
            #pragma unroll
            for (int dx = 0; dx < 5; dx++)
                ws += d2[(y + dy) * W_ + (x + dx)];
        float hm = sqrtf(ws / 25.0f);
        out[96 + bt * NP_ + tid] = hm;
        mymax = hm; mymin = hm; myidx = tid;
    }

    __shared__ float smx[1024];
    __shared__ float smn[1024];
    __shared__ int   six[1024];
    smx[tid] = mymax; smn[tid] = mymin; six[tid] = myidx;
    __syncthreads();
    for (int st = 512; st > 0; st >>= 1) {
        if (tid < st) {
            smx[tid] = fmaxf(smx[tid], smx[tid + st]);
            float v = smn[tid + st];
            int  ix = six[tid + st];
            if (v < smn[tid] || (v == smn[tid] && ix < six[tid])) {
                smn[tid] = v; six[tid] = ix;
            }
        }
        __syncthreads();
    }

    if (tid == 0) {
        out[bt] = smx[0];
        int idx = six[0];
        out[32 + bt * 2 + 0] = (float)(idx % WP_);  // x_argmin
        out[32 + bt * 2 + 1] = (float)(idx / WP_);  // y_argmin
    }
}

// ---------------------------------------------------------------------------
extern "C" void kernel_launch(void* const* d_in, const int* in_sizes, int n_in,
                              void* d_out, int out_size)
{
    const float* l     = (const float*)d_in[0];
    const float* r     = (const float*)d_in[1];
    const float* gamma = (const float*)d_in[2];
    // d_in[3] = bn_beta: cancels exactly in (l_bn - r_bn), unused.
    float* out = (float*)d_out;

    fused_kernel<<<T_ * NPART, NTHR>>>(l, r, gamma);
    reduce_kernel<<<BT_ * 8, 1024>>>();
    finalize_kernel<<<BT_, 1024>>>(out);
}

// round 12
// speedup vs baseline: 1.1338x; 1.1338x over previous
#include <cuda_runtime.h>
#include <cstdint>
#include <math.h>

// Problem constants
#define B_   8
#define T_   4
#define C_   512
#define H_   32
#define W_   32
#define HW_  1024
#define BT_  32          // B_*T_
#define NPART 64         // channel partitions per t
#define CPP   (C_/NPART) // 8 channels per block
#define HP_  28
#define WP_  28
#define NP_  784         // 28*28
#define BN_EPS 1e-5f
#define BSTRIDE ((size_t)T_ * C_ * HW_)   // elements between consecutive b
#define BSTR4   (BSTRIDE/4)               // in float4 units
#define NTHR 512

// Scratch (allocation-free rule: __device__ globals)
__device__ float g_d2[BT_ * HW_];            // 128 KB accumulation buffer

// ---------------------------------------------------------------------------
// Zero kernel: clears g_d2 every call (atomic accumulation target).
// ---------------------------------------------------------------------------
__global__ void zero_kernel()
{
    const int i = blockIdx.x * blockDim.x + threadIdx.x;
    reinterpret_cast<float4*>(g_d2)[i] = make_float4(0.f, 0.f, 0.f, 0.f);
}

// ---------------------------------------------------------------------------
// Fused kernel (R9 structure): ONE DRAM pass + per-channel hot-L2 re-read.
// grid: T_*NPART = 256 blocks (2/SM), 512 threads.
// Block (t,p) owns 8 channels. Per channel:
//   stats: stream 4+4 float4, warp shuffle-reduce, lane0 -> smem
//   ONE barrier (parity double-buffered warp-sum arrays)
//   all-warp combine -> A,B,D; d^2: re-read same data from hot L2, accumulate.
// Ends with atomicAdd into g_d2 (no partials materialization, no reduce pass).
// beta cancels exactly in (l_bn - r_bn).
// ---------------------------------------------------------------------------
__global__ __launch_bounds__(NTHR, 2) void fused_kernel(
    const float* __restrict__ l, const float* __restrict__ r,
    const float* __restrict__ gamma)
{
    const int t   = blockIdx.x >> 6;        // / NPART
    const int p   = blockIdx.x & (NPART-1);
    const int tid = threadIdx.x;
    const int lane = tid & 31;
    const int wid  = tid >> 5;              // 0..15

    // This thread's 4 float4 slots: s_i = tid + i*512 -> (b, hw4)
    int bvec[4], hw4[4];
    size_t offb[4];
    #pragma unroll
    for (int i = 0; i < 4; i++) {
        const int s = tid + i * NTHR;
        bvec[i] = s >> 8;
        hw4[i]  = s & 255;
        offb[i] = (size_t)bvec[i] * BSTR4 + hw4[i];
    }

    __shared__ float w0[2][16], w1[2][16], w2[2][16], w3[2][16];
    __shared__ float sgamma[CPP];
    if (tid < CPP) sgamma[tid] = gamma[p * CPP + tid];

    float acc[16];
    #pragma unroll
    for (int k = 0; k < 16; k++) acc[k] = 0.f;

    const float4* l4 = reinterpret_cast<const float4*>(l);
    const float4* r4 = reinterpret_cast<const float4*>(r);

    #pragma unroll 1
    for (int ci = 0; ci < CPP; ci++) {
        const int c = p * CPP + ci;
        const size_t chbase = ((size_t)(t * C_ + c)) * (HW_ / 4);

        // ---- stats pass: stream 4+4 float4, accumulate
        float sl = 0.f, ql = 0.f, sr = 0.f, qr = 0.f;
        #pragma unroll
        for (int i = 0; i < 4; i++) {
            float4 lv = l4[offb[i] + chbase];
            float4 rv = r4[offb[i] + chbase];
            sl += (lv.x + lv.y) + (lv.z + lv.w);
            sr += (rv.x + rv.y) + (rv.z + rv.w);
            ql = fmaf(lv.x, lv.x, ql); ql = fmaf(lv.y, lv.y, ql);
            ql = fmaf(lv.z, lv.z, ql); ql = fmaf(lv.w, lv.w, ql);
            qr = fmaf(rv.x, rv.x, qr); qr = fmaf(rv.y, rv.y, qr);
            qr = fmaf(rv.z, rv.z, qr); qr = fmaf(rv.w, rv.w, qr);
        }

        // ---- warp shuffle reduction
        #pragma unroll
        for (int o = 16; o > 0; o >>= 1) {
            sl += __shfl_xor_sync(0xffffffffu, sl, o);
            ql += __shfl_xor_sync(0xffffffffu, ql, o);
            sr += __shfl_xor_sync(0xffffffffu, sr, o);
            qr += __shfl_xor_sync(0xffffffffu, qr, o);
        }

        const int par = ci & 1;
        if (lane == 0) {
            w0[par][wid] = sl; w1[par][wid] = ql;
            w2[par][wid] = sr; w3[par][wid] = qr;
        }
        __syncthreads();   // the ONLY barrier per channel

        // ---- every warp combines the 16 warp-sums
        float a0 = (lane < 16) ? w0[par][lane] : 0.f;
        float a1 = (lane < 16) ? w1[par][lane] : 0.f;
        float a2 = (lane < 16) ? w2[par][lane] : 0.f;
        float a3 = (lane < 16) ? w3[par][lane] : 0.f;
        #pragma unroll
        for (int o = 8; o > 0; o >>= 1) {
            a0 += __shfl_xor_sync(0xffffffffu, a0, o);
            a1 += __shfl_xor_sync(0xffffffffu, a1, o);
            a2 += __shfl_xor_sync(0xffffffffu, a2, o);
            a3 += __shfl_xor_sync(0xffffffffu, a3, o);
        }
        a0 = __shfl_sync(0xffffffffu, a0, 0);
        a1 = __shfl_sync(0xffffffffu, a1, 0);
        a2 = __shfl_sync(0xffffffffu, a2, 0);
        a3 = __shfl_sync(0xffffffffu, a3, 0);

        const float inv_n = 1.f / (float)(B_ * HW_);   // 1/8192
        float mul  = a0 * inv_n;
        float mur  = a2 * inv_n;
        float varl = fmaf(-mul, mul, a1 * inv_n);
        float varr = fmaf(-mur, mur, a3 * inv_n);
        float g  = sgamma[ci];
        float A  = g / sqrtf(varl + BN_EPS);
        float Bc = g / sqrtf(varr + BN_EPS);
        float D  = A * mul - Bc * mur;

        // ---- d^2 pass: re-read same data (hot in L2), accumulate
        #pragma unroll
        for (int i = 0; i < 4; i++) {
            float4 lv = l4[offb[i] + chbase];
            float4 rv = r4[offb[i] + chbase];
            float d;
            d = fmaf(A, lv.x, fmaf(-Bc, rv.x, -D)); acc[i*4+0] = fmaf(d, d, acc[i*4+0]);
            d = fmaf(A, lv.y, fmaf(-Bc, rv.y, -D)); acc[i*4+1] = fmaf(d, d, acc[i*4+1]);
            d = fmaf(A, lv.z, fmaf(-Bc, rv.z, -D)); acc[i*4+2] = fmaf(d, d, acc[i*4+2]);
            d = fmaf(A, lv.w, fmaf(-Bc, rv.w, -D)); acc[i*4+3] = fmaf(d, d, acc[i*4+3]);
        }
    }

    // ---- accumulate directly into g_d2 via atomics (spread addresses;
    //      64-way contention per address spread across block completion times)
    #pragma unroll
    for (int i = 0; i < 4; i++) {
        float* dst = g_d2 + (bvec[i] * T_ + t) * HW_ + hw4[i] * 4;
        atomicAdd(dst + 0, acc[i*4+0]);
        atomicAdd(dst + 1, acc[i*4+1]);
        atomicAdd(dst + 2, acc[i*4+2]);
        atomicAdd(dst + 3, acc[i*4+3]);
    }
}

// ---------------------------------------------------------------------------
// Finalize: 5x5 window sum, sqrt, max + first-argmin.
// grid: 32 blocks (one per (b,t)), 1024 threads.
// Output layout (float32, tuple order):
//   [0,32) values (B,T) | [32,96) coords (B,T,2) [x,y] | [96,25184) heatmap
// ---------------------------------------------------------------------------
__global__ __launch_bounds__(1024) void finalize_kernel(float* __restrict__ out)
{
    const int bt  = blockIdx.x;
    const int tid = threadIdx.x;

    __shared__ float d2[HW_];
    d2[tid] = g_d2[bt * HW_ + tid];
    __syncthreads();

    float mymax = -3.0e38f;
    float mymin =  3.0e38f;
    int   myidx = 0x7fffffff;

    if (tid < NP_) {
        const int y = tid / WP_;
        const int x = tid % WP_;
        float ws = 0.f;
        #pragma unroll
        for (int dy = 0; dy < 5; dy++)
            #pragma unroll
            for (int dx = 0; dx < 5; dx++)
                ws += d2[(y + dy) * W_ + (x + dx)];
        float hm = sqrtf(ws / 25.0f);
        out[96 + bt * NP_ + tid] = hm;
        mymax = hm; mymin = hm; myidx = tid;
    }

    __shared__ float smx[1024];
    __shared__ float smn[1024];
    __shared__ int   six[1024];
    smx[tid] = mymax; smn[tid] = mymin; six[tid] = myidx;
    __syncthreads();
    for (int st = 512; st > 0; st >>= 1) {
        if (tid < st) {
            smx[tid] = fmaxf(smx[tid], smx[tid + st]);
            float v = smn[tid + st];
            int  ix = six[tid + st];
            if (v < smn[tid] || (v == smn[tid] && ix < six[tid])) {
                smn[tid] = v; six[tid] = ix;
            }
        }
        __syncthreads();
    }

    if (tid == 0) {
        out[bt] = smx[0];
        int idx = six[0];
        out[32 + bt * 2 + 0] = (float)(idx % WP_);  // x_argmin
        out[32 + bt * 2 + 1] = (float)(idx / WP_);  // y_argmin
    }
}

// ---------------------------------------------------------------------------
extern "C" void kernel_launch(void* const* d_in, const int* in_sizes, int n_in,
                              void* d_out, int out_size)
{
    const float* l     = (const float*)d_in[0];
    const float* r     = (const float*)d_in[1];
    const float* gamma = (const float*)d_in[2];
    // d_in[3] = bn_beta: cancels exactly in (l_bn - r_bn), unused.
    float* out = (float*)d_out;

    zero_kernel<<<(BT_ * HW_ / 4) / 256, 256>>>();
    fused_kernel<<<T_ * NPART, NTHR>>>(l, r, gamma);
    finalize_kernel<<<BT_, 1024>>>(out);
}

// round 13
// speedup vs baseline: 1.3279x; 1.1712x over previous
#include <cuda_runtime.h>
#include <cstdint>
#include <math.h>

// Problem constants
#define B_   8
#define T_   4
#define C_   512
#define H_   32
#define W_   32
#define HW_  1024
#define BT_  32          // B_*T_
#define NPART 64         // channel partitions per t
#define CPP   (C_/NPART) // 8 channels per block
#define HP_  28
#define WP_  28
#define NP_  784         // 28*28
#define BN_EPS 1e-5f
#define BSTRIDE ((size_t)T_ * C_ * HW_)   // elements between consecutive b
#define BSTR4   (BSTRIDE/4)               // in float4 units
#define NTHR 512

// Scratch (allocation-free rule: __device__ globals)
__device__ float g_part[NPART][BT_ * HW_];   // 8 MB

// ---------------------------------------------------------------------------
// Fused kernel (R9 structure, best known): ONE DRAM pass + hot-L2 re-read.
// grid: T_*NPART = 256 blocks (2/SM), 512 threads.
// Block (t,p) owns 8 channels. Per channel:
//   stats: stream 4+4 float4, warp shuffle-reduce, lane0 -> smem
//   ONE barrier (parity double-buffered warp-sum arrays)
//   all-warp combine -> A,B,D; d^2: re-read same data from hot L2, accumulate.
// beta cancels exactly in (l_bn - r_bn).
// ---------------------------------------------------------------------------
__global__ __launch_bounds__(NTHR, 2) void fused_kernel(
    const float* __restrict__ l, const float* __restrict__ r,
    const float* __restrict__ gamma)
{
    const int t   = blockIdx.x >> 6;        // / NPART
    const int p   = blockIdx.x & (NPART-1);
    const int tid = threadIdx.x;
    const int lane = tid & 31;
    const int wid  = tid >> 5;              // 0..15

    // This thread's 4 float4 slots: s_i = tid + i*512 -> (b, hw4)
    int bvec[4], hw4[4];
    size_t offb[4];
    #pragma unroll
    for (int i = 0; i < 4; i++) {
        const int s = tid + i * NTHR;
        bvec[i] = s >> 8;
        hw4[i]  = s & 255;
        offb[i] = (size_t)bvec[i] * BSTR4 + hw4[i];
    }

    __shared__ float w0[2][16], w1[2][16], w2[2][16], w3[2][16];
    __shared__ float sgamma[CPP];
    if (tid < CPP) sgamma[tid] = gamma[p * CPP + tid];

    float acc[16];
    #pragma unroll
    for (int k = 0; k < 16; k++) acc[k] = 0.f;

    const float4* l4 = reinterpret_cast<const float4*>(l);
    const float4* r4 = reinterpret_cast<const float4*>(r);

    #pragma unroll 1
    for (int ci = 0; ci < CPP; ci++) {
        const int c = p * CPP + ci;
        const size_t chbase = ((size_t)(t * C_ + c)) * (HW_ / 4);

        // ---- stats pass: stream 4+4 float4, accumulate
        float sl = 0.f, ql = 0.f, sr = 0.f, qr = 0.f;
        #pragma unroll
        for (int i = 0; i < 4; i++) {
            float4 lv = l4[offb[i] + chbase];
            float4 rv = r4[offb[i] + chbase];
            sl += (lv.x + lv.y) + (lv.z + lv.w);
            sr += (rv.x + rv.y) + (rv.z + rv.w);
            ql = fmaf(lv.x, lv.x, ql); ql = fmaf(lv.y, lv.y, ql);
            ql = fmaf(lv.z, lv.z, ql); ql = fmaf(lv.w, lv.w, ql);
            qr = fmaf(rv.x, rv.x, qr); qr = fmaf(rv.y, rv.y, qr);
            qr = fmaf(rv.z, rv.z, qr); qr = fmaf(rv.w, rv.w, qr);
        }

        // ---- warp shuffle reduction
        #pragma unroll
        for (int o = 16; o > 0; o >>= 1) {
            sl += __shfl_xor_sync(0xffffffffu, sl, o);
            ql += __shfl_xor_sync(0xffffffffu, ql, o);
            sr += __shfl_xor_sync(0xffffffffu, sr, o);
            qr += __shfl_xor_sync(0xffffffffu, qr, o);
        }

        const int par = ci & 1;
        if (lane == 0) {
            w0[par][wid] = sl; w1[par][wid] = ql;
            w2[par][wid] = sr; w3[par][wid] = qr;
        }
        __syncthreads();   // the ONLY barrier per channel

        // ---- every warp combines the 16 warp-sums
        float a0 = (lane < 16) ? w0[par][lane] : 0.f;
        float a1 = (lane < 16) ? w1[par][lane] : 0.f;
        float a2 = (lane < 16) ? w2[par][lane] : 0.f;
        float a3 = (lane < 16) ? w3[par][lane] : 0.f;
        #pragma unroll
        for (int o = 8; o > 0; o >>= 1) {
            a0 += __shfl_xor_sync(0xffffffffu, a0, o);
            a1 += __shfl_xor_sync(0xffffffffu, a1, o);
            a2 += __shfl_xor_sync(0xffffffffu, a2, o);
            a3 += __shfl_xor_sync(0xffffffffu, a3, o);
        }
        a0 = __shfl_sync(0xffffffffu, a0, 0);
        a1 = __shfl_sync(0xffffffffu, a1, 0);
        a2 = __shfl_sync(0xffffffffu, a2, 0);
        a3 = __shfl_sync(0xffffffffu, a3, 0);

        const float inv_n = 1.f / (float)(B_ * HW_);   // 1/8192
        float mul  = a0 * inv_n;
        float mur  = a2 * inv_n;
        float varl = fmaf(-mul, mul, a1 * inv_n);
        float varr = fmaf(-mur, mur, a3 * inv_n);
        float g  = sgamma[ci];
        float A  = g / sqrtf(varl + BN_EPS);
        float Bc = g / sqrtf(varr + BN_EPS);
        float D  = A * mul - Bc * mur;

        // ---- d^2 pass: re-read same data (hot in L2), accumulate
        #pragma unroll
        for (int i = 0; i < 4; i++) {
            float4 lv = l4[offb[i] + chbase];
            float4 rv = r4[offb[i] + chbase];
            float d;
            d = fmaf(A, lv.x, fmaf(-Bc, rv.x, -D)); acc[i*4+0] = fmaf(d, d, acc[i*4+0]);
            d = fmaf(A, lv.y, fmaf(-Bc, rv.y, -D)); acc[i*4+1] = fmaf(d, d, acc[i*4+1]);
            d = fmaf(A, lv.z, fmaf(-Bc, rv.z, -D)); acc[i*4+2] = fmaf(d, d, acc[i*4+2]);
            d = fmaf(A, lv.w, fmaf(-Bc, rv.w, -D)); acc[i*4+3] = fmaf(d, d, acc[i*4+3]);
        }
    }

    // ---- write partials: g_part[p][(b*T+t)*1024 + hw] as float4
    float4* gp = reinterpret_cast<float4*>(g_part[p]);
    #pragma unroll
    for (int i = 0; i < 4; i++) {
        gp[(bvec[i] * T_ + t) * (HW_/4) + hw4[i]] =
            make_float4(acc[i*4+0], acc[i*4+1], acc[i*4+2], acc[i*4+3]);
    }
}

// ---------------------------------------------------------------------------
// Merged finalize: layer-sum (MLP-structured) + 5x5 window + max/argmin.
// grid: 32 blocks (one per (b,t)), 1024 threads.
// Phase 1: tid = (lg = tid>>8 in [0,4), p4 = tid&255). Each thread sums 16
//          layers for its float4 position -> 16 independent LDG.128 in flight.
// Phase 2: 4-way smem combine -> d2[1024].
// Phase 3: 5x5 window, sqrt, block max + first-argmin.
// Output layout (float32, tuple order):
//   [0,32) values (B,T) | [32,96) coords (B,T,2) [x,y] | [96,25184) heatmap
// ---------------------------------------------------------------------------
__global__ __launch_bounds__(1024) void finalize_kernel(float* __restrict__ out)
{
    const int bt  = blockIdx.x;
    const int tid = threadIdx.x;
    const int lg  = tid >> 8;       // layer group 0..3 (16 layers each)
    const int p4  = tid & 255;      // float4 position 0..255

    __shared__ float4 sred[4][256];
    __shared__ float  d2[HW_];

    // Phase 1: sum 16 layers (independent float4 loads -> deep MLP)
    {
        const int base4 = bt * (HW_ / 4) + p4;
        float4 a = make_float4(0.f, 0.f, 0.f, 0.f);
        #pragma unroll
        for (int k = 0; k < 16; k++) {
            const float4 v = reinterpret_cast<const float4*>(g_part[lg * 16 + k])[base4];
            a.x += v.x; a.y += v.y; a.z += v.z; a.w += v.w;
        }
        sred[lg][p4] = a;
    }
    __syncthreads();

    // Phase 2: combine 4 layer-groups
    if (tid < 256) {
        float4 a = sred[0][tid], b = sred[1][tid], c = sred[2][tid], e = sred[3][tid];
        d2[tid * 4 + 0] = (a.x + b.x) + (c.x + e.x);
        d2[tid * 4 + 1] = (a.y + b.y) + (c.y + e.y);
        d2[tid * 4 + 2] = (a.z + b.z) + (c.z + e.z);
        d2[tid * 4 + 3] = (a.w + b.w) + (c.w + e.w);
    }
    __syncthreads();

    // Phase 3: window + reductions
    float mymax = -3.0e38f;
    float mymin =  3.0e38f;
    int   myidx = 0x7fffffff;

    if (tid < NP_) {
        const int y = tid / WP_;
        const int x = tid % WP_;
        float ws = 0.f;
        #pragma unroll
        for (int dy = 0; dy < 5; dy++)
            #pragma unroll
            for (int dx = 0; dx < 5; dx++)
                ws += d2[(y + dy) * W_ + (x + dx)];
        float hm = sqrtf(ws / 25.0f);
        out[96 + bt * NP_ + tid] = hm;
        mymax = hm; mymin = hm; myidx = tid;
    }

    __shared__ float smx[1024];
    __shared__ float smn[1024];
    __shared__ int   six[1024];
    smx[tid] = mymax; smn[tid] = mymin; six[tid] = myidx;
    __syncthreads();
    for (int st = 512; st > 0; st >>= 1) {
        if (tid < st) {
            smx[tid] = fmaxf(smx[tid], smx[tid + st]);
            float v = smn[tid + st];
            int  ix = six[tid + st];
            if (v < smn[tid] || (v == smn[tid] && ix < six[tid])) {
                smn[tid] = v; six[tid] = ix;
            }
        }
        __syncthreads();
    }

    if (tid == 0) {
        out[bt] = smx[0];
        int idx = six[0];
        out[32 + bt * 2 + 0] = (float)(idx % WP_);  // x_argmin
        out[32 + bt * 2 + 1] = (float)(idx / WP_);  // y_argmin
    }
}

// ---------------------------------------------------------------------------
extern "C" void kernel_launch(void* const* d_in, const int* in_sizes, int n_in,
                              void* d_out, int out_size)
{
    const float* l     = (const float*)d_in[0];
    const float* r     = (const float*)d_in[1];
    const float* gamma = (const float*)d_in[2];
    // d_in[3] = bn_beta: cancels exactly in (l_bn - r_bn), unused.
    float* out = (float*)d_out;

    fused_kernel<<<T_ * NPART, NTHR>>>(l, r, gamma);
    finalize_kernel<<<BT_, 1024>>>(out);
}